// round 1
// baseline (speedup 1.0000x reference)
#include <cuda_runtime.h>
#include <math.h>

#define Bn 4
#define Cn 256
#define Hn 100
#define Wn 100
#define Pn (Hn * Wn)
#define C4 (Cn / 4)   // 64 float4 per row

// Channels-last scratch: xt[b, p, c], 4*10000*256 floats = 40.96 MB
__device__ float g_xt[Bn * Pn * Cn];

// ---------------------------------------------------------------------------
// Kernel 1: transpose x [B, C, P] -> g_xt [B, P, C]   (P = H*W = 10000)
// ---------------------------------------------------------------------------
__global__ void transpose_kernel(const float* __restrict__ x) {
    __shared__ float tile[32][33];
    int b  = blockIdx.z;
    int p0 = blockIdx.x * 32;
    int c0 = blockIdx.y * 32;        // C=256 divisible by 32 -> no c bounds check
    int tx = threadIdx.x;
    int ty = threadIdx.y;

    #pragma unroll
    for (int i = 0; i < 32; i += 8) {
        int c = c0 + ty + i;
        int p = p0 + tx;
        float v = 0.0f;
        if (p < Pn) v = x[(b * Cn + c) * Pn + p];
        tile[ty + i][tx] = v;
    }
    __syncthreads();
    #pragma unroll
    for (int i = 0; i < 32; i += 8) {
        int p = p0 + ty + i;
        int c = c0 + tx;
        if (p < Pn) g_xt[(b * Pn + p) * Cn + c] = tile[tx][ty + i];
    }
}

// ---------------------------------------------------------------------------
// Kernel 2: one 64-thread block per output pixel.
// Each thread owns 4 channels (float4). 9 taps, 4 bilinear corners each.
// OOB corners: weight = 0, address clamped (deform-conv zero padding).
// ---------------------------------------------------------------------------
__global__ void __launch_bounds__(64) deform_kernel(
    const float* __restrict__ off,   // [B, 18, H, W]
    const float* __restrict__ w0,    // [1, C]
    const float* __restrict__ b0,    // [1]
    float* __restrict__ out)         // [B, 1, H, W]
{
    const int pix = blockIdx.x;              // 0 .. B*P-1
    const int b   = pix / Pn;
    const int p   = pix - b * Pn;
    const int h   = p / Wn;
    const int w   = p - h * Wn;
    const int t   = threadIdx.x;             // 0 .. 63

    __shared__ int   s_a[9][4];              // corner base index / 4 (float4 units)
    __shared__ float s_w[9][4];              // bilinear weights (0 if OOB)
    __shared__ float s_red[2];

    if (t < 9) {
        const int k = t;
        float dy = off[((b * 18 + 2 * k    ) * Pn) + p];
        float dx = off[((b * 18 + 2 * k + 1) * Pn) + p];
        float py = (float)h + (float)(k / 3 - 1) + dy;
        float px = (float)w + (float)(k % 3 - 1) + dx;
        float fy = floorf(py);
        float fx = floorf(px);
        int y0 = (int)fy;
        int x0 = (int)fx;
        float wy = py - fy;
        float wx = px - fx;

        bool vy0 = (y0     >= 0) && (y0     < Hn);
        bool vy1 = (y0 + 1 >= 0) && (y0 + 1 < Hn);
        bool vx0 = (x0     >= 0) && (x0     < Wn);
        bool vx1 = (x0 + 1 >= 0) && (x0 + 1 < Wn);

        s_w[k][0] = (vy0 && vx0) ? (1.0f - wy) * (1.0f - wx) : 0.0f;
        s_w[k][1] = (vy0 && vx1) ? (1.0f - wy) * wx           : 0.0f;
        s_w[k][2] = (vy1 && vx0) ? wy * (1.0f - wx)           : 0.0f;
        s_w[k][3] = (vy1 && vx1) ? wy * wx                    : 0.0f;

        int ry0 = min(max(y0,     0), Hn - 1);
        int ry1 = min(max(y0 + 1, 0), Hn - 1);
        int rx0 = min(max(x0,     0), Wn - 1);
        int rx1 = min(max(x0 + 1, 0), Wn - 1);

        int bp = b * Pn;
        // base index in float4 units: ((bp + y*W + x) * Cn) / 4 = (bp + y*W + x) * 64
        s_a[k][0] = (bp + ry0 * Wn + rx0) * C4;
        s_a[k][1] = (bp + ry0 * Wn + rx1) * C4;
        s_a[k][2] = (bp + ry1 * Wn + rx0) * C4;
        s_a[k][3] = (bp + ry1 * Wn + rx1) * C4;
    }
    __syncthreads();

    const float4* __restrict__ xt4 = (const float4*)g_xt;

    float4 m = make_float4(-INFINITY, -INFINITY, -INFINITY, -INFINITY);

    #pragma unroll
    for (int k = 0; k < 9; k++) {
        float4 v00 = xt4[s_a[k][0] + t];
        float4 v01 = xt4[s_a[k][1] + t];
        float4 v10 = xt4[s_a[k][2] + t];
        float4 v11 = xt4[s_a[k][3] + t];
        float w00 = s_w[k][0], w01 = s_w[k][1], w10 = s_w[k][2], w11 = s_w[k][3];

        float sx = v00.x * w00 + v01.x * w01 + v10.x * w10 + v11.x * w11;
        float sy = v00.y * w00 + v01.y * w01 + v10.y * w10 + v11.y * w11;
        float sz = v00.z * w00 + v01.z * w01 + v10.z * w10 + v11.z * w11;
        float sw = v00.w * w00 + v01.w * w01 + v10.w * w10 + v11.w * w11;

        m.x = fmaxf(m.x, sx);
        m.y = fmaxf(m.y, sy);
        m.z = fmaxf(m.z, sz);
        m.w = fmaxf(m.w, sw);
    }

    // dot with w0 over this thread's 4 channels
    float4 wv = ((const float4*)w0)[t];
    float s = m.x * wv.x + m.y * wv.y + m.z * wv.z + m.w * wv.w;

    // reduce 64 values: intra-warp shuffle, then 2 partials via shared
    #pragma unroll
    for (int o = 16; o > 0; o >>= 1)
        s += __shfl_down_sync(0xffffffffu, s, o);

    if ((t & 31) == 0) s_red[t >> 5] = s;
    __syncthreads();

    if (t == 0) {
        float z = s_red[0] + s_red[1] + b0[0];
        out[pix] = 1.0f / (1.0f + expf(-z));
    }
}

// ---------------------------------------------------------------------------
extern "C" void kernel_launch(void* const* d_in, const int* in_sizes, int n_in,
                              void* d_out, int out_size) {
    const float* x   = (const float*)d_in[0];   // [4, 256, 100, 100]
    const float* off = (const float*)d_in[1];   // [4, 18, 100, 100]
    const float* w0  = (const float*)d_in[2];   // [1, 256]
    const float* b0  = (const float*)d_in[3];   // [1]
    float* out = (float*)d_out;                 // [4, 1, 100, 100]

    dim3 tgrid((Pn + 31) / 32, Cn / 32, Bn);    // (313, 8, 4)
    transpose_kernel<<<tgrid, dim3(32, 8)>>>(x);

    deform_kernel<<<Bn * Pn, 64>>>(off, w0, b0, out);
}

// round 3
// speedup vs baseline: 1.6386x; 1.6386x over previous
#include <cuda_runtime.h>
#include <cuda_fp16.h>
#include <math.h>

#define Bn 4
#define Cn 256
#define Hn 100
#define Wn 100
#define Pn (Hn * Wn)
#define ROW_F4 (Cn * 2 / 16)   // 32 float4 (16B) units per 512B fp16 row

// Channels-last fp16 scratch: g_xh[b, p, c], 4*10000*256 halves = 20.5 MB
__device__ __half g_xh[Bn * Pn * Cn];

// ---------------------------------------------------------------------------
// Kernel 1: transpose+convert x [B, C, P] fp32 -> g_xh [B, P, C] fp16
// ---------------------------------------------------------------------------
__global__ void transpose_kernel(const float* __restrict__ x) {
    __shared__ float tile[32][33];
    int b  = blockIdx.z;
    int p0 = blockIdx.x * 32;
    int c0 = blockIdx.y * 32;
    int tx = threadIdx.x;
    int ty = threadIdx.y;

    #pragma unroll
    for (int i = 0; i < 32; i += 8) {
        int c = c0 + ty + i;
        int p = p0 + tx;
        float v = 0.0f;
        if (p < Pn) v = x[(b * Cn + c) * Pn + p];
        tile[ty + i][tx] = v;
    }
    __syncthreads();
    #pragma unroll
    for (int i = 0; i < 32; i += 8) {
        int p = p0 + ty + i;
        int c = c0 + tx;
        if (p < Pn) g_xh[(b * Pn + p) * Cn + c] = __float2half(tile[tx][ty + i]);
    }
}

// ---------------------------------------------------------------------------
// Kernel 2: one warp per output pixel (4 warps / 128-thread block).
// Each lane owns 8 channels; one warp-wide float4 load = one 512B corner row.
// Bilinear blend + tap-max in half2, final dot + reduction in fp32.
// ---------------------------------------------------------------------------
__global__ void __launch_bounds__(128) deform_kernel(
    const float* __restrict__ off,   // [B, 18, H, W]
    const float* __restrict__ w0,    // [1, C]
    const float* __restrict__ b0,    // [1]
    float* __restrict__ out)         // [B, 1, H, W]
{
    const int warp = threadIdx.x >> 5;
    const int lane = threadIdx.x & 31;
    const int pix  = blockIdx.x * 4 + warp;     // 0 .. B*P-1
    const int b    = pix / Pn;
    const int p    = pix - b * Pn;
    const int h    = p / Wn;
    const int w    = p - h * Wn;

    __shared__ int     s_a[4][9][4];            // corner row base (float4 units)
    __shared__ __half2 s_w[4][9][4];            // bilinear weights (0 if OOB)

    if (lane < 9) {
        const int k = lane;
        float dy = off[((b * 18 + 2 * k    ) * Pn) + p];
        float dx = off[((b * 18 + 2 * k + 1) * Pn) + p];
        float py = (float)h + (float)(k / 3 - 1) + dy;
        float px = (float)w + (float)(k % 3 - 1) + dx;
        float fy = floorf(py);
        float fx = floorf(px);
        int y0 = (int)fy;
        int x0 = (int)fx;
        float wy = py - fy;
        float wx = px - fx;

        bool vy0 = (y0     >= 0) && (y0     < Hn);
        bool vy1 = (y0 + 1 >= 0) && (y0 + 1 < Hn);
        bool vx0 = (x0     >= 0) && (x0     < Wn);
        bool vx1 = (x0 + 1 >= 0) && (x0 + 1 < Wn);

        float w00 = (vy0 && vx0) ? (1.0f - wy) * (1.0f - wx) : 0.0f;
        float w01 = (vy0 && vx1) ? (1.0f - wy) * wx           : 0.0f;
        float w10 = (vy1 && vx0) ? wy * (1.0f - wx)           : 0.0f;
        float w11 = (vy1 && vx1) ? wy * wx                    : 0.0f;
        s_w[warp][k][0] = __float2half2_rn(w00);
        s_w[warp][k][1] = __float2half2_rn(w01);
        s_w[warp][k][2] = __float2half2_rn(w10);
        s_w[warp][k][3] = __float2half2_rn(w11);

        int ry0 = min(max(y0,     0), Hn - 1);
        int ry1 = min(max(y0 + 1, 0), Hn - 1);
        int rx0 = min(max(x0,     0), Wn - 1);
        int rx1 = min(max(x0 + 1, 0), Wn - 1);

        int bp = b * Pn;
        s_a[warp][k][0] = (bp + ry0 * Wn + rx0) * ROW_F4;
        s_a[warp][k][1] = (bp + ry0 * Wn + rx1) * ROW_F4;
        s_a[warp][k][2] = (bp + ry1 * Wn + rx0) * ROW_F4;
        s_a[warp][k][3] = (bp + ry1 * Wn + rx1) * ROW_F4;
    }
    __syncwarp();

    const float4* __restrict__ xh4 = (const float4*)g_xh;

    const __half2 ninf = __float2half2_rn(-INFINITY);
    __half2 m0 = ninf, m1 = ninf, m2 = ninf, m3 = ninf;

    #pragma unroll
    for (int k = 0; k < 9; k++) {
        float4 r00 = xh4[s_a[warp][k][0] + lane];
        float4 r01 = xh4[s_a[warp][k][1] + lane];
        float4 r10 = xh4[s_a[warp][k][2] + lane];
        float4 r11 = xh4[s_a[warp][k][3] + lane];
        __half2 w00 = s_w[warp][k][0];
        __half2 w01 = s_w[warp][k][1];
        __half2 w10 = s_w[warp][k][2];
        __half2 w11 = s_w[warp][k][3];

        const __half2* h00 = (const __half2*)&r00;
        const __half2* h01 = (const __half2*)&r01;
        const __half2* h10 = (const __half2*)&r10;
        const __half2* h11 = (const __half2*)&r11;

        #pragma unroll
        for (int j = 0; j < 4; j++) {
            __half2 s = __hmul2(h00[j], w00);
            s = __hfma2(h01[j], w01, s);
            s = __hfma2(h10[j], w10, s);
            s = __hfma2(h11[j], w11, s);
            __half2 mj = (j == 0) ? m0 : (j == 1) ? m1 : (j == 2) ? m2 : m3;
            mj = __hmax2(mj, s);
            if (j == 0) m0 = mj; else if (j == 1) m1 = mj;
            else if (j == 2) m2 = mj; else m3 = mj;
        }
    }

    // dot with w0 over this lane's 8 channels [lane*8, lane*8+8)
    float4 wa = ((const float4*)w0)[lane * 2];
    float4 wb = ((const float4*)w0)[lane * 2 + 1];

    float2 f0 = __half22float2(m0);
    float2 f1 = __half22float2(m1);
    float2 f2 = __half22float2(m2);
    float2 f3 = __half22float2(m3);

    float s = f0.x * wa.x + f0.y * wa.y + f1.x * wa.z + f1.y * wa.w
            + f2.x * wb.x + f2.y * wb.y + f3.x * wb.z + f3.y * wb.w;

    #pragma unroll
    for (int o = 16; o > 0; o >>= 1)
        s += __shfl_down_sync(0xffffffffu, s, o);

    if (lane == 0) {
        float z = s + b0[0];
        out[pix] = 1.0f / (1.0f + expf(-z));
    }
}

// ---------------------------------------------------------------------------
extern "C" void kernel_launch(void* const* d_in, const int* in_sizes, int n_in,
                              void* d_out, int out_size) {
    const float* x   = (const float*)d_in[0];   // [4, 256, 100, 100]
    const float* off = (const float*)d_in[1];   // [4, 18, 100, 100]
    const float* w0  = (const float*)d_in[2];   // [1, 256]
    const float* b0  = (const float*)d_in[3];   // [1]
    float* out = (float*)d_out;                 // [4, 1, 100, 100]

    dim3 tgrid((Pn + 31) / 32, Cn / 32, Bn);    // (313, 8, 4)
    transpose_kernel<<<tgrid, dim3(32, 8)>>>(x);

    deform_kernel<<<Bn * Pn / 4, 128>>>(off, w0, b0, out);
}